// round 1
// baseline (speedup 1.0000x reference)
#include <cuda_runtime.h>
#include <cstdint>

// Problem constants (fixed by the dataset: B=262144, D=32, R=16)
#define BATCH 262144
#define R 16

// Bit layout of a batch's 32 selector bits (bit i = X[b][i]):
//   bits 0..5   -> U table   (x0 chooses core_first column; x1..x5 choose cores_mid[0..4])
//   bits 6..25  -> 4 mid groups of 5 bits (cores_mid[5..24])
//   bits 26..31 -> W table   (x26..x30 choose cores_mid[25..29]; x31 chooses core_last)
//
// Per batch:  v = U[j0];  v = v @ T_k[idx_k] (k=0..3);  out = dot(v, W[j1])

// Scratch (device globals — no allocation allowed)
__device__ float    g_U[64 * 16];
__device__ float    g_T[4 * 32 * 256];
__device__ float    g_W[64 * 16];
__device__ unsigned g_masks[BATCH];

// ---------------------------------------------------------------------------
// Table builders (tiny; rebuilt every launch, deterministic)
// ---------------------------------------------------------------------------

// U[j][s] = (e_{x0} F) * M_{0,x1} * ... * M_{4,x5}   (left-to-right matvecs)
__global__ void build_U(const float* __restrict__ cf, const float* __restrict__ cm) {
    int j = threadIdx.x;
    if (j >= 64) return;
    float v[R], nv[R];
    int x0 = j & 1;
    for (int r = 0; r < R; r++) v[r] = cf[r * 2 + x0];           // core_first[0][r][x0]
    for (int i = 0; i < 5; i++) {
        int b = (j >> (i + 1)) & 1;
        for (int s = 0; s < R; s++) {
            float acc = 0.f;
            for (int r = 0; r < R; r++)
                acc += v[r] * cm[((i * R + r) * R + s) * 2 + b]; // cores_mid[i][r][s][b]
            nv[s] = acc;
        }
        for (int s = 0; s < R; s++) v[s] = nv[s];
    }
    for (int s = 0; s < R; s++) g_U[j * R + s] = v[s];
}

// T_k[idx] = M_{5+5k, b0} * ... * M_{9+5k, b4}.  One thread per (idx, output col s):
// compute column s right-to-left as matvecs.
__global__ void build_T(const float* __restrict__ cm) {
    int k   = blockIdx.x;          // 0..3
    int idx = threadIdx.x >> 4;    // 0..31
    int s   = threadIdx.x & 15;    // 0..15
    float v[R], nv[R];
    int c4 = 5 + 5 * k + 4;
    int b4 = (idx >> 4) & 1;
    for (int t = 0; t < R; t++) v[t] = cm[((c4 * R + t) * R + s) * 2 + b4];
    for (int jj = 3; jj >= 0; jj--) {
        int c = 5 + 5 * k + jj;
        int b = (idx >> jj) & 1;
        for (int r = 0; r < R; r++) {
            float acc = 0.f;
            for (int t = 0; t < R; t++)
                acc += cm[((c * R + r) * R + t) * 2 + b] * v[t];
            nv[r] = acc;
        }
        for (int r = 0; r < R; r++) v[r] = nv[r];
    }
    for (int r = 0; r < R; r++)
        g_T[(k * 32 + idx) * 256 + r * R + s] = v[r];
}

// W[j][r] = (M_{25,b0} * ... * M_{29,b4} * lastcol_{b5})[r]  (right-to-left matvecs)
__global__ void build_W(const float* __restrict__ cm, const float* __restrict__ cl) {
    int j = threadIdx.x;
    if (j >= 64) return;
    float v[R], nv[R];
    int b5 = (j >> 5) & 1;
    for (int t = 0; t < R; t++) v[t] = cl[t * 2 + b5];           // core_last[t][0][b5]
    for (int i = 4; i >= 0; i--) {
        int c = 25 + i;
        int b = (j >> i) & 1;
        for (int r = 0; r < R; r++) {
            float acc = 0.f;
            for (int t = 0; t < R; t++)
                acc += cm[((c * R + r) * R + t) * 2 + b] * v[t];
            nv[r] = acc;
        }
        for (int r = 0; r < R; r++) v[r] = nv[r];
    }
    for (int r = 0; r < R; r++) g_W[j * R + r] = v[r];
}

// ---------------------------------------------------------------------------
// Pack X[B,32] (int32 0/1, row-major) into one uint32 mask per batch.
// Warp handles 32 batches; iteration i reads bit 'lane' of batch base+i
// (fully coalesced 128B line) and ballots it into a mask.
// ---------------------------------------------------------------------------
__global__ void pack_masks(const int* __restrict__ X) {
    int warp = (blockIdx.x * blockDim.x + threadIdx.x) >> 5;
    int lane = threadIdx.x & 31;
    int base = warp * 32;
    #pragma unroll 4
    for (int i = 0; i < 32; i++) {
        int val = X[(base + i) * 32 + lane];
        unsigned mm = __ballot_sync(0xffffffffu, val);
        if (lane == i) g_masks[base + i] = mm;
    }
}

// ---------------------------------------------------------------------------
// Main kernel.
// smem layout (floats): sT[4*32*260] (mat stride padded 256->260 to spread
// wide-bank groups by idx), sU[64*20], sW[64*20] (row stride 16->20, keeps
// 16B alignment for float4 loads).
// ---------------------------------------------------------------------------
#define ST_FLOATS (4 * 32 * 260)
#define SUW_FLOATS (64 * 20)
#define SMEM_FLOATS (ST_FLOATS + 2 * SUW_FLOATS)
#define SMEM_BYTES (SMEM_FLOATS * 4)

extern __shared__ float sm_buf[];

__global__ __launch_bounds__(1024, 1) void tt_main(float* __restrict__ out, int B) {
    float* sT = sm_buf;
    float* sU = sm_buf + ST_FLOATS;
    float* sW = sU + SUW_FLOATS;

    // Stage tables into shared with padding
    for (int i = threadIdx.x; i < 4 * 32 * 256; i += 1024)
        sT[(i >> 8) * 260 + (i & 255)] = g_T[i];
    for (int i = threadIdx.x; i < 64 * 16; i += 1024) {
        sU[(i >> 4) * 20 + (i & 15)] = g_U[i];
        sW[(i >> 4) * 20 + (i & 15)] = g_W[i];
    }
    __syncthreads();

    long long start = (long long)blockIdx.x * B / gridDim.x;
    long long end   = (long long)(blockIdx.x + 1) * B / gridDim.x;

    for (long long b = start + threadIdx.x; b < end; b += 1024) {
        unsigned m = g_masks[b];

        // init: v = U[m & 63]
        const float4* u = (const float4*)(sU + (m & 63u) * 20);
        float4 u0 = u[0], u1 = u[1], u2 = u[2], u3 = u[3];
        float v[16];
        v[0]=u0.x; v[1]=u0.y; v[2]=u0.z; v[3]=u0.w;
        v[4]=u1.x; v[5]=u1.y; v[6]=u1.z; v[7]=u1.w;
        v[8]=u2.x; v[9]=u2.y; v[10]=u2.z; v[11]=u2.w;
        v[12]=u3.x; v[13]=u3.y; v[14]=u3.z; v[15]=u3.w;
        m >>= 6;

        #pragma unroll
        for (int k = 0; k < 4; k++) {
            const float4* M = (const float4*)(sT + (k * 32 + (m & 31u)) * 260);
            m >>= 5;
            float4 a0 = {0,0,0,0}, a1 = {0,0,0,0}, a2 = {0,0,0,0}, a3 = {0,0,0,0};
            #pragma unroll
            for (int r = 0; r < 16; r++) {
                float vr = v[r];
                float4 m0 = M[r * 4 + 0];
                float4 m1 = M[r * 4 + 1];
                float4 m2 = M[r * 4 + 2];
                float4 m3 = M[r * 4 + 3];
                a0.x += vr * m0.x; a0.y += vr * m0.y; a0.z += vr * m0.z; a0.w += vr * m0.w;
                a1.x += vr * m1.x; a1.y += vr * m1.y; a1.z += vr * m1.z; a1.w += vr * m1.w;
                a2.x += vr * m2.x; a2.y += vr * m2.y; a2.z += vr * m2.z; a2.w += vr * m2.w;
                a3.x += vr * m3.x; a3.y += vr * m3.y; a3.z += vr * m3.z; a3.w += vr * m3.w;
            }
            v[0]=a0.x; v[1]=a0.y; v[2]=a0.z; v[3]=a0.w;
            v[4]=a1.x; v[5]=a1.y; v[6]=a1.z; v[7]=a1.w;
            v[8]=a2.x; v[9]=a2.y; v[10]=a2.z; v[11]=a2.w;
            v[12]=a3.x; v[13]=a3.y; v[14]=a3.z; v[15]=a3.w;
        }

        // final: dot(v, W[m & 63])   (m now holds bits 26..31 at positions 0..5)
        const float4* w = (const float4*)(sW + (m & 63u) * 20);
        float4 w0 = w[0], w1 = w[1], w2 = w[2], w3 = w[3];
        float acc =
            v[0]*w0.x + v[1]*w0.y + v[2]*w0.z + v[3]*w0.w +
            v[4]*w1.x + v[5]*w1.y + v[6]*w1.z + v[7]*w1.w +
            v[8]*w2.x + v[9]*w2.y + v[10]*w2.z + v[11]*w2.w +
            v[12]*w3.x + v[13]*w3.y + v[14]*w3.z + v[15]*w3.w;

        out[b] = acc;
    }
}

// ---------------------------------------------------------------------------
extern "C" void kernel_launch(void* const* d_in, const int* in_sizes, int n_in,
                              void* d_out, int out_size) {
    const int*   X  = (const int*)d_in[0];
    const float* cf = (const float*)d_in[1];
    const float* cm = (const float*)d_in[2];
    const float* cl = (const float*)d_in[3];
    float* out = (float*)d_out;

    int B = in_sizes[0] / 32;   // 262144

    build_U<<<1, 64>>>(cf, cm);
    build_T<<<4, 512>>>(cm);
    build_W<<<1, 64>>>(cm, cl);
    pack_masks<<<B / 256, 256>>>(X);

    cudaFuncSetAttribute(tt_main, cudaFuncAttributeMaxDynamicSharedMemorySize, SMEM_BYTES);
    tt_main<<<148, 1024, SMEM_BYTES>>>(out, B);
}